// round 13
// baseline (speedup 1.0000x reference)
#include <cuda_runtime.h>
#include <cuda_fp16.h>
#include <cstdint>

#define B_   8
#define CIN  64
#define COUT 128
#define L_   18
#define LV   16
#define H_   32
#define W_   32
#define HW   1024
#define NH   2
#define DQ   9
#define DV   8
#define KSPL 2            // logit K split

// Scratch (static device globals; no runtime allocation allowed)
__device__ float g_q[B_*COUT*L_*HW];                // 75.5 MB
__device__ float g_k[B_*COUT*L_*HW];                // 75.5 MB
__device__ float g_v[B_*COUT*LV*HW];                // 67 MB
__device__ float g_lp[KSPL*B_*NH*DQ*COUT*COUT];     // 18.9 MB
__device__ float g_attn[B_*NH*COUT*COUT];           // 1 MB

typedef unsigned long long ull;

// ---------------------------------------------------------------------------
// fp16 split helpers
// ---------------------------------------------------------------------------
__device__ __forceinline__ uint32_t f2h2(float x0, float x1) {
    uint32_t r;
    asm("cvt.rn.f16x2.f32 %0, %1, %2;" : "=r"(r) : "f"(x1), "f"(x0));
    return r;   // lo half = x0, hi half = x1 (memory order)
}
__device__ __forceinline__ float2 h2f2(uint32_t u) {
    __half2 h = *(__half2*)&u;
    return __half22float2(h);
}
__device__ __forceinline__ void split2(float x0, float x1, uint32_t& hi, uint32_t& lo) {
    hi = f2h2(x0, x1);
    float2 hf = h2f2(hi);
    lo = f2h2(x0 - hf.x, x1 - hf.y);
}

// mma.sync m16n8k16 fp16 (baseline PTX, works on plain sm_103)
__device__ __forceinline__ void mma_f16(float* d, const uint32_t* a,
                                        uint32_t b0, uint32_t b1) {
    asm volatile(
        "mma.sync.aligned.m16n8k16.row.col.f32.f16.f16.f32 "
        "{%0,%1,%2,%3}, {%4,%5,%6,%7}, {%8,%9}, {%0,%1,%2,%3};"
        : "+f"(d[0]), "+f"(d[1]), "+f"(d[2]), "+f"(d[3])
        : "r"(a[0]), "r"(a[1]), "r"(a[2]), "r"(a[3]), "r"(b0), "r"(b1));
}

// f32x2 helpers (out_kernel)
__device__ __forceinline__ ull pack2(float x, float y) {
    ull r; asm("mov.b64 %0, {%1, %2};" : "=l"(r) : "f"(x), "f"(y)); return r;
}
__device__ __forceinline__ float2 unpack2(ull v) {
    float2 r; asm("mov.b64 {%0, %1}, %2;" : "=f"(r.x), "=f"(r.y) : "l"(v)); return r;
}
__device__ __forceinline__ void ffma2(ull& d, ull a, ull b) {
    asm("fma.rn.f32x2 %0, %1, %2, %0;" : "+l"(d) : "l"(a), "l"(b));
}

__device__ __forceinline__ uint32_t smem_u32(const void* p) {
    uint32_t a;
    asm("{ .reg .u64 t; cvta.to.shared.u64 t, %1; cvt.u32.u64 %0, t; }"
        : "=r"(a) : "l"(p));
    return a;
}
#define CP_COMMIT() asm volatile("cp.async.commit_group;" ::: "memory")
#define CP_WAIT0()  asm volatile("cp.async.wait_group 0;" ::: "memory")

#define KC    32          // K elems per chunk
#define SW    20          // logit smem row stride (u32 words)
#define AST   40          // conv A f32 smem row stride (floats): LDS.64 conflict-free
#define BST   132         // conv B f32 smem k-row stride (floats): conflict-free
#define A_STG (128*AST)   // 5120 floats per stage
#define B_STG (32*BST)    // 4224 floats per stage
#define CONV_SMEM ((2*A_STG + 2*B_STG)*4)   // 74752 bytes

// ---------------------------------------------------------------------------
// Conv MMA core: f32 tiles in smem, split to fp16 hi/lo at fragment load.
// A [co][k] stride AST, B [k][px] stride BST.
// acc += Ah*Bh + Al*Bh + Ah*Bl over the 32-k chunk.
// ---------------------------------------------------------------------------
__device__ __forceinline__ void mma_stage(
    float acc[2][8][4], const float* As, const float* Bs,
    int wm, int wn, int lid)
{
    const int qr = lid >> 2;
    const int qc = lid & 3;
#pragma unroll
    for (int ks = 0; ks < 2; ks++) {
        const int kb = ks << 4;
        uint32_t ah[2][4], al[2][4];
#pragma unroll
        for (int mt = 0; mt < 2; mt++) {
            int r0 = (wm << 5) + (mt << 4) + qr;
            float2 x0 = *(const float2*)&As[r0*AST + kb + 2*qc];
            float2 x1 = *(const float2*)&As[(r0 + 8)*AST + kb + 2*qc];
            float2 x2 = *(const float2*)&As[r0*AST + kb + 8 + 2*qc];
            float2 x3 = *(const float2*)&As[(r0 + 8)*AST + kb + 8 + 2*qc];
            split2(x0.x, x0.y, ah[mt][0], al[mt][0]);
            split2(x1.x, x1.y, ah[mt][1], al[mt][1]);
            split2(x2.x, x2.y, ah[mt][2], al[mt][2]);
            split2(x3.x, x3.y, ah[mt][3], al[mt][3]);
        }
#pragma unroll
        for (int np = 0; np < 4; np++) {
            uint32_t bh[2][2], bl[2][2];
#pragma unroll
            for (int j = 0; j < 2; j++) {
                int nt = (np << 1) + j;
                int n  = (wn << 6) + (nt << 3) + qr;
                float f0 = Bs[(kb + 2*qc)*BST + n];
                float f1 = Bs[(kb + 2*qc + 1)*BST + n];
                split2(f0, f1, bh[j][0], bl[j][0]);
                f0 = Bs[(kb + 8 + 2*qc)*BST + n];
                f1 = Bs[(kb + 8 + 2*qc + 1)*BST + n];
                split2(f0, f1, bh[j][1], bl[j][1]);
            }
#pragma unroll
            for (int j = 0; j < 2; j++) {
                int nt = (np << 1) + j;
                mma_f16(acc[0][nt], ah[0], bh[j][0], bh[j][1]);
                mma_f16(acc[1][nt], ah[1], bh[j][0], bh[j][1]);
                mma_f16(acc[0][nt], al[0], bh[j][0], bh[j][1]);
                mma_f16(acc[1][nt], al[1], bh[j][0], bh[j][1]);
                mma_f16(acc[0][nt], ah[0], bl[j][0], bl[j][1]);
                mma_f16(acc[1][nt], ah[1], bl[j][0], bl[j][1]);
            }
        }
    }
}

// ---------------------------------------------------------------------------
// Implicit-GEMM conv: cp.async double-buffered f32 staging + fp16x3 MMA.
// D[co=128, hw=128] = W[co, K] * P[hw, K], K = CIN*TAPS.
// grid (8 hw-tiles, LOUT, B_), block 256, 2 CTAs/SM.
// ---------------------------------------------------------------------------
template<int TAPS, int LOUT>
__global__ __launch_bounds__(256, 2) void conv_mma_kernel(
    const float* __restrict__ in, const float* __restrict__ wgt,
    const float* __restrict__ bias, float* __restrict__ dst, float scale)
{
    constexpr int KSEG = CIN * TAPS;          // 576 or 1728
    constexpr int NCHUNK = KSEG / KC;         // 18 or 54
    extern __shared__ float smem[];
    float* Asm = smem;                        // 2 stages x 128 x AST
    float* Bsm = smem + 2*A_STG;              // 2 stages x 32 x BST

    const int tid = threadIdx.x;
    const int wid = tid >> 5;
    const int lid = tid & 31;
    const int wm  = wid & 3;
    const int wn  = wid >> 2;
    const int l   = blockIdx.y;
    const int b   = blockIdx.z;
    const int hw0 = blockIdx.x << 7;

    const float* inb = in + (size_t)b*CIN*L_*HW + (size_t)l*HW;
    // B build mapping: lanes sweep pixels (coalesced global, conflict-free STS)
    const int px  = tid & 127;
    const int kq  = tid >> 7;                 // 0/1
    const int bh_ = (hw0 + px) >> 5;
    const int bw_ = px & 31;

    float acc[2][8][4];
#pragma unroll
    for (int i = 0; i < 2; i++)
#pragma unroll
        for (int j = 0; j < 8; j++)
#pragma unroll
            for (int r = 0; r < 4; r++) acc[i][j][r] = 0.f;

    auto issueA = [&](int tb, float* As) {
#pragma unroll
        for (int q = 0; q < 4; q++) {
            int idx = tid + (q << 8);
            int row = idx >> 3;
            int kg  = idx & 7;
            const float* src = wgt + (size_t)row * KSEG + tb + (kg << 2);
            uint32_t ds = smem_u32(As + row*AST + (kg << 2));
            asm volatile("cp.async.cg.shared.global [%0], [%1], 16;"
                         :: "r"(ds), "l"(src));
        }
    };
    auto issueB = [&](int tb, float* Bs) {
#pragma unroll
        for (int it = 0; it < 16; it++) {
            int k   = (it << 1) + kq;
            int t   = tb + k;
            int ci  = t / TAPS;
            int tap = t - ci * TAPS;
            int dl, dh, dw;
            if (TAPS == 27) { dl = tap / 9; int r = tap - dl * 9; dh = r / 3; dw = r - dh * 3; }
            else            { dl = 0; dh = tap / 3; dw = tap - dh * 3; }
            int hh = bh_ + dh - 1, ww = bw_ + dw - 1;
            bool ok = ((unsigned)hh < (unsigned)H_) && ((unsigned)ww < (unsigned)W_);
            const float* src = ok ? (inb + ((size_t)ci * L_ + dl) * HW + hh * W_ + ww)
                                  : in;
            int sz = ok ? 4 : 0;
            uint32_t ds = smem_u32(Bs + k*BST + px);
            asm volatile("cp.async.ca.shared.global [%0], [%1], 4, %2;"
                         :: "r"(ds), "l"(src), "r"(sz));
        }
    };

    issueA(0, Asm);
    issueB(0, Bsm);
    CP_COMMIT();

#pragma unroll 1
    for (int c = 0; c < NCHUNK; c++) {
        const int s = c & 1;
        CP_WAIT0();
        __syncthreads();
        if (c + 1 < NCHUNK) {
            issueA((c + 1) * KC, Asm + (s ^ 1) * A_STG);
            issueB((c + 1) * KC, Bsm + (s ^ 1) * B_STG);
            CP_COMMIT();
        }
        mma_stage(acc, Asm + s * A_STG, Bsm + s * B_STG, wm, wn, lid);
        __syncthreads();
    }

    // Epilogue
#pragma unroll
    for (int mt = 0; mt < 2; mt++) {
        int co = (wm << 5) + (mt << 4) + (lid >> 2);
        float bi0 = bias[co];
        float bi1 = bias[co + 8];
        float* d0 = dst + (((size_t)b * COUT + co)     * LOUT + l) * HW + hw0;
        float* d1 = dst + (((size_t)b * COUT + co + 8) * LOUT + l) * HW + hw0;
#pragma unroll
        for (int nt = 0; nt < 8; nt++) {
            int colp = (wn << 6) + (nt << 3) + ((lid & 3) << 1);
            *(float2*)(d0 + colp) = make_float2((acc[mt][nt][0] + bi0) * scale,
                                                (acc[mt][nt][1] + bi0) * scale);
            *(float2*)(d1 + colp) = make_float2((acc[mt][nt][2] + bi1) * scale,
                                                (acc[mt][nt][3] + bi1) * scale);
        }
    }
}

// ---------------------------------------------------------------------------
// Logit (unchanged from passing round-12 version)
// ---------------------------------------------------------------------------
__device__ __forceinline__ void mma_chunk(
    float acc[2][8][4],
    const uint32_t* Ah, const uint32_t* Al,
    const uint32_t* Bh, const uint32_t* Bl,
    int wm, int wn, int lid)
{
    const int qr = lid >> 2;
    const int qc = lid & 3;
#pragma unroll
    for (int ks = 0; ks < 2; ks++) {
        const int base = ks << 3;
        uint32_t ah[2][4], al[2][4];
#pragma unroll
        for (int mt = 0; mt < 2; mt++) {
            int r0 = (wm << 5) + (mt << 4) + qr;
            int w0 = r0 * SW + base + qc;
            int w1 = (r0 + 8) * SW + base + qc;
            ah[mt][0] = Ah[w0];     ah[mt][1] = Ah[w1];
            ah[mt][2] = Ah[w0 + 4]; ah[mt][3] = Ah[w1 + 4];
            al[mt][0] = Al[w0];     al[mt][1] = Al[w1];
            al[mt][2] = Al[w0 + 4]; al[mt][3] = Al[w1 + 4];
        }
        uint32_t bf[8][2];
#pragma unroll
        for (int nt = 0; nt < 8; nt++) {
            int n = (wn << 6) + (nt << 3) + qr;
            int w = n * SW + base + qc;
            bf[nt][0] = Bh[w]; bf[nt][1] = Bh[w + 4];
        }
#pragma unroll
        for (int nt = 0; nt < 8; nt++) {
            mma_f16(acc[0][nt], ah[0], bf[nt][0], bf[nt][1]);
            mma_f16(acc[1][nt], ah[1], bf[nt][0], bf[nt][1]);
        }
#pragma unroll
        for (int nt = 0; nt < 8; nt++) {
            mma_f16(acc[0][nt], al[0], bf[nt][0], bf[nt][1]);
            mma_f16(acc[1][nt], al[1], bf[nt][0], bf[nt][1]);
        }
#pragma unroll
        for (int nt = 0; nt < 8; nt++) {
            int n = (wn << 6) + (nt << 3) + qr;
            int w = n * SW + base + qc;
            bf[nt][0] = Bl[w]; bf[nt][1] = Bl[w + 4];
        }
#pragma unroll
        for (int nt = 0; nt < 8; nt++) {
            mma_f16(acc[0][nt], ah[0], bf[nt][0], bf[nt][1]);
            mma_f16(acc[1][nt], ah[1], bf[nt][0], bf[nt][1]);
        }
    }
}

__global__ __launch_bounds__(256, 1) void logit_mma_kernel(
    const float* __restrict__ q, const float* __restrict__ k, float* __restrict__ lp)
{
    constexpr int NCHUNK = HW / (KC * KSPL);  // 16
    __shared__ uint32_t Ah[128*SW], Al[128*SW], Bh[128*SW], Bl[128*SW];

    const int tid = threadIdx.x;
    const int wid = tid >> 5;
    const int lid = tid & 31;
    const int wm  = wid & 3;
    const int wn  = wid >> 2;
    const int ck  = blockIdx.x / (B_*NH*DQ);
    const int bnd = blockIdx.x % (B_*NH*DQ);
    const int d   = bnd % DQ;
    const int bn  = bnd / DQ;
    const int n_  = bn & 1;
    const int b   = bn >> 1;
    const int ldep = n_ * DQ + d;

    const float* qb = q + ((size_t)b * COUT * L_ + ldep) * HW;
    const float* kb = k + ((size_t)b * COUT * L_ + ldep) * HW;

    float acc[2][8][4];
#pragma unroll
    for (int i = 0; i < 2; i++)
#pragma unroll
        for (int j = 0; j < 8; j++)
#pragma unroll
            for (int r = 0; r < 4; r++) acc[i][j][r] = 0.f;

    const int kp_b = tid & 15;
    const int rw_b = tid >> 4;
    const int base0 = ck * (HW/KSPL);

    float aw[16], bx[16];
    auto loadQK = [&](int tb) {
#pragma unroll
        for (int qq = 0; qq < 8; qq++) {
            int row = rw_b + (qq << 4);
            float2 va = *(const float2*)(qb + (size_t)row * (L_*HW) + tb + (kp_b << 1));
            aw[2*qq] = va.x; aw[2*qq + 1] = va.y;
            float2 vb = *(const float2*)(kb + (size_t)row * (L_*HW) + tb + (kp_b << 1));
            bx[2*qq] = vb.x; bx[2*qq + 1] = vb.y;
        }
    };

    loadQK(base0);

#pragma unroll 1
    for (int c = 0; c < NCHUNK; c++) {
#pragma unroll
        for (int qq = 0; qq < 8; qq++) {
            int row = rw_b + (qq << 4);
            uint32_t hi, lo;
            split2(aw[2*qq], aw[2*qq + 1], hi, lo);
            Ah[row*SW + kp_b] = hi;
            Al[row*SW + kp_b] = lo;
            split2(bx[2*qq], bx[2*qq + 1], hi, lo);
            Bh[row*SW + kp_b] = hi;
            Bl[row*SW + kp_b] = lo;
        }
        __syncthreads();
        if (c + 1 < NCHUNK) loadQK(base0 + (c + 1) * KC);
        mma_chunk(acc, Ah, Al, Bh, Bl, wm, wn, lid);
        __syncthreads();
    }

    float* o = lp + (size_t)blockIdx.x * COUT * COUT;
#pragma unroll
    for (int mt = 0; mt < 2; mt++) {
        int cc = (wm << 5) + (mt << 4) + (lid >> 2);
#pragma unroll
        for (int nt = 0; nt < 8; nt++) {
            int m = (wn << 6) + (nt << 3) + ((lid & 3) << 1);
            *(float2*)(o + (size_t)cc * COUT + m) =
                make_float2(acc[mt][nt][0], acc[mt][nt][1]);
            *(float2*)(o + (size_t)(cc + 8) * COUT + m) =
                make_float2(acc[mt][nt][2], acc[mt][nt][3]);
        }
    }
}

// ---------------------------------------------------------------------------
// Sum KSPL*DQ partials + row softmax over m. One block per (bn, c).
// ---------------------------------------------------------------------------
__global__ __launch_bounds__(128) void softmax_kernel(
    const float* __restrict__ lp, float* __restrict__ attn)
{
    const int row = blockIdx.x;
    const int bn  = row >> 7;
    const int c   = row & 127;
    const int m   = threadIdx.x;

    float s = 0.f;
#pragma unroll
    for (int ch = 0; ch < KSPL; ch++)
#pragma unroll
        for (int dd = 0; dd < DQ; dd++)
            s += lp[(((size_t)(ch*(B_*NH*DQ) + bn*DQ + dd))*COUT + c)*COUT + m];

    __shared__ float red[128];
    red[m] = s;
    __syncthreads();
    for (int off = 64; off > 0; off >>= 1) {
        if (m < off) red[m] = fmaxf(red[m], red[m + off]);
        __syncthreads();
    }
    float mx = red[0];
    __syncthreads();
    float e = expf(s - mx);
    red[m] = e;
    __syncthreads();
    for (int off = 64; off > 0; off >>= 1) {
        if (m < off) red[m] = red[m] + red[m + off];
        __syncthreads();
    }
    attn[row*COUT + m] = e / red[0];
}

// ---------------------------------------------------------------------------
// out[b,c,n*8+d,hw] = sum_m attn[bn,c,m] * v[b,m,n*8+d,hw]  (f32x2 scalar)
// ---------------------------------------------------------------------------
__global__ __launch_bounds__(256) void out_kernel(
    const float* __restrict__ attn, const float* __restrict__ v, float* __restrict__ out)
{
    const int tile = blockIdx.x;
    const int bn   = blockIdx.y;
    const int b    = bn >> 1;
    const int n    = bn & 1;
    const int d    = (tile << 6) >> 10;
    const int hw0  = (tile << 6) & 1023;
    const int tid  = threadIdx.x;
    const int px   = tid & 63;
    const int cg   = tid >> 6;
    const int c0   = cg << 5;
    const int hw   = hw0 + px;

    __shared__ float As2[64*132];
    const float* ab = attn + bn*COUT*COUT;
    const float* vb = v + ((size_t)b*COUT*LV + n*DV + d)*HW + hw;

    ull acc2[16];
#pragma unroll
    for (int j = 0; j < 16; j++) acc2[j] = 0ull;

    for (int mc = 0; mc < 2; mc++) {
        __syncthreads();
        for (int i = tid; i < 64*128; i += 256) {
            int ml = i & 63;
            int c  = i >> 6;
            As2[ml*132 + c] = ab[c*COUT + (mc << 6) + ml];
        }
        __syncthreads();
#pragma unroll 4
        for (int ml = 0; ml < 64; ml++) {
            float vv = vb[((size_t)((mc << 6) + ml))*(LV*HW)];
            ull vp = pack2(vv, vv);
            const ull* ap = (const ull*)&As2[ml*132 + c0];
#pragma unroll
            for (int jj = 0; jj < 16; jj++)
                ffma2(acc2[jj], ap[jj], vp);
        }
    }
    float* ob = out + (((size_t)b*COUT + c0)*(NH*DV) + n*DV + d)*HW + hw;
#pragma unroll
    for (int jj = 0; jj < 16; jj++) {
        float2 a = unpack2(acc2[jj]);
        ob[(size_t)(2*jj)    *(NH*DV*HW)] = a.x;
        ob[(size_t)(2*jj + 1)*(NH*DV*HW)] = a.y;
    }
}

// ---------------------------------------------------------------------------
extern "C" void kernel_launch(void* const* d_in, const int* in_sizes, int n_in,
                              void* d_out, int out_size)
{
    const float* input  = (const float*)d_in[0];
    const float* memory = (const float*)d_in[1];
    const float* wq = (const float*)d_in[2];
    const float* bq = (const float*)d_in[3];
    const float* wk = (const float*)d_in[4];
    const float* bk = (const float*)d_in[5];
    const float* wv = (const float*)d_in[6];
    const float* bv = (const float*)d_in[7];
    float* out = (float*)d_out;

    float *pq, *pk, *pv, *plp, *pattn;
    cudaGetSymbolAddress((void**)&pq,    g_q);
    cudaGetSymbolAddress((void**)&pk,    g_k);
    cudaGetSymbolAddress((void**)&pv,    g_v);
    cudaGetSymbolAddress((void**)&plp,   g_lp);
    cudaGetSymbolAddress((void**)&pattn, g_attn);

    cudaFuncSetAttribute(conv_mma_kernel<9, L_>,
                         cudaFuncAttributeMaxDynamicSharedMemorySize, CONV_SMEM);
    cudaFuncSetAttribute(conv_mma_kernel<27, LV>,
                         cudaFuncAttributeMaxDynamicSharedMemorySize, CONV_SMEM);

    conv_mma_kernel<9, L_> <<<dim3(8, L_, B_), 256, CONV_SMEM>>>(input,  wq, bq, pq, 0.5f);
    conv_mma_kernel<9, L_> <<<dim3(8, L_, B_), 256, CONV_SMEM>>>(memory, wk, bk, pk, 1.0f);
    conv_mma_kernel<27, LV><<<dim3(8, LV, B_), 256, CONV_SMEM>>>(memory, wv, bv, pv, 1.0f);
    logit_mma_kernel       <<<KSPL*B_*NH*DQ, 256>>>(pq, pk, plp);
    softmax_kernel         <<<B_*NH*COUT, 128>>>(plp, pattn);
    out_kernel             <<<dim3(128, B_*NH), 256>>>(pattn, pv, out);
}

// round 14
// speedup vs baseline: 1.0451x; 1.0451x over previous
#include <cuda_runtime.h>
#include <cuda_fp16.h>
#include <cstdint>

#define B_   8
#define CIN  64
#define COUT 128
#define L_   18
#define LV   16
#define H_   32
#define W_   32
#define HW   1024
#define NH   2
#define DQ   9
#define DV   8
#define KSPL 2            // logit K split

// Scratch (static device globals; no runtime allocation allowed)
__device__ float g_q[B_*COUT*L_*HW];                // 75.5 MB
__device__ float g_k[B_*COUT*L_*HW];                // 75.5 MB
__device__ float g_v[B_*COUT*LV*HW];                // 67 MB
__device__ float g_lp[KSPL*B_*NH*DQ*COUT*COUT];     // 18.9 MB
__device__ float g_attn[B_*NH*COUT*COUT];           // 1 MB

typedef unsigned long long ull;

// ---------------------------------------------------------------------------
// fp16 split helpers
// ---------------------------------------------------------------------------
__device__ __forceinline__ uint32_t f2h2(float x0, float x1) {
    uint32_t r;
    asm("cvt.rn.f16x2.f32 %0, %1, %2;" : "=r"(r) : "f"(x1), "f"(x0));
    return r;   // lo half = x0, hi half = x1 (memory order)
}
__device__ __forceinline__ float2 h2f2(uint32_t u) {
    __half2 h = *(__half2*)&u;
    return __half22float2(h);
}
__device__ __forceinline__ void split2(float x0, float x1, uint32_t& hi, uint32_t& lo) {
    hi = f2h2(x0, x1);
    float2 hf = h2f2(hi);
    lo = f2h2(x0 - hf.x, x1 - hf.y);
}

// mma.sync m16n8k16 fp16 (baseline PTX, works on plain sm_103)
__device__ __forceinline__ void mma_f16(float* d, const uint32_t* a,
                                        uint32_t b0, uint32_t b1) {
    asm volatile(
        "mma.sync.aligned.m16n8k16.row.col.f32.f16.f16.f32 "
        "{%0,%1,%2,%3}, {%4,%5,%6,%7}, {%8,%9}, {%0,%1,%2,%3};"
        : "+f"(d[0]), "+f"(d[1]), "+f"(d[2]), "+f"(d[3])
        : "r"(a[0]), "r"(a[1]), "r"(a[2]), "r"(a[3]), "r"(b0), "r"(b1));
}

// f32x2 helpers (out_kernel)
__device__ __forceinline__ ull pack2(float x, float y) {
    ull r; asm("mov.b64 %0, {%1, %2};" : "=l"(r) : "f"(x), "f"(y)); return r;
}
__device__ __forceinline__ float2 unpack2(ull v) {
    float2 r; asm("mov.b64 {%0, %1}, %2;" : "=f"(r.x), "=f"(r.y) : "l"(v)); return r;
}
__device__ __forceinline__ void ffma2(ull& d, ull a, ull b) {
    asm("fma.rn.f32x2 %0, %1, %2, %0;" : "+l"(d) : "l"(a), "l"(b));
}

#define KC   32          // K elems per chunk
#define SW   20          // A / logit smem row stride (u32 words = k-pairs + pad)
#define SWB  136         // conv B smem k-pair-row stride (u32 words = pixels + pad)

// ---------------------------------------------------------------------------
// MMA core, conv variant: A [co][kp] stride SW, B [kp][px] stride SWB.
// acc += Ah*Bh + Al*Bh + Ah*Bl over the 32-k chunk in smem.
// ---------------------------------------------------------------------------
__device__ __forceinline__ void mma_chunk_bk(
    float acc[2][8][4],
    const uint32_t* Ah, const uint32_t* Al,
    const uint32_t* Bh, const uint32_t* Bl,
    int wm, int wn, int lid)
{
    const int qr = lid >> 2;
    const int qc = lid & 3;
#pragma unroll
    for (int ks = 0; ks < 2; ks++) {
        const int base = ks << 3;
        uint32_t ah[2][4], al[2][4];
#pragma unroll
        for (int mt = 0; mt < 2; mt++) {
            int r0 = (wm << 5) + (mt << 4) + qr;
            int w0 = r0 * SW + base + qc;
            int w1 = (r0 + 8) * SW + base + qc;
            ah[mt][0] = Ah[w0];     ah[mt][1] = Ah[w1];
            ah[mt][2] = Ah[w0 + 4]; ah[mt][3] = Ah[w1 + 4];
            al[mt][0] = Al[w0];     al[mt][1] = Al[w1];
            al[mt][2] = Al[w0 + 4]; al[mt][3] = Al[w1 + 4];
        }
        uint32_t bf[8][2];
#pragma unroll
        for (int nt = 0; nt < 8; nt++) {
            int n = (wn << 6) + (nt << 3) + qr;
            bf[nt][0] = Bh[(base + qc) * SWB + n];
            bf[nt][1] = Bh[(base + qc + 4) * SWB + n];
        }
#pragma unroll
        for (int nt = 0; nt < 8; nt++) {
            mma_f16(acc[0][nt], ah[0], bf[nt][0], bf[nt][1]);
            mma_f16(acc[1][nt], ah[1], bf[nt][0], bf[nt][1]);
        }
#pragma unroll
        for (int nt = 0; nt < 8; nt++) {
            mma_f16(acc[0][nt], al[0], bf[nt][0], bf[nt][1]);
            mma_f16(acc[1][nt], al[1], bf[nt][0], bf[nt][1]);
        }
#pragma unroll
        for (int nt = 0; nt < 8; nt++) {
            int n = (wn << 6) + (nt << 3) + qr;
            bf[nt][0] = Bl[(base + qc) * SWB + n];
            bf[nt][1] = Bl[(base + qc + 4) * SWB + n];
        }
#pragma unroll
        for (int nt = 0; nt < 8; nt++) {
            mma_f16(acc[0][nt], ah[0], bf[nt][0], bf[nt][1]);
            mma_f16(acc[1][nt], ah[1], bf[nt][0], bf[nt][1]);
        }
    }
}

// Logit variant: both A and B in [row][kp] layout, stride SW.
__device__ __forceinline__ void mma_chunk(
    float acc[2][8][4],
    const uint32_t* Ah, const uint32_t* Al,
    const uint32_t* Bh, const uint32_t* Bl,
    int wm, int wn, int lid)
{
    const int qr = lid >> 2;
    const int qc = lid & 3;
#pragma unroll
    for (int ks = 0; ks < 2; ks++) {
        const int base = ks << 3;
        uint32_t ah[2][4], al[2][4];
#pragma unroll
        for (int mt = 0; mt < 2; mt++) {
            int r0 = (wm << 5) + (mt << 4) + qr;
            int w0 = r0 * SW + base + qc;
            int w1 = (r0 + 8) * SW + base + qc;
            ah[mt][0] = Ah[w0];     ah[mt][1] = Ah[w1];
            ah[mt][2] = Ah[w0 + 4]; ah[mt][3] = Ah[w1 + 4];
            al[mt][0] = Al[w0];     al[mt][1] = Al[w1];
            al[mt][2] = Al[w0 + 4]; al[mt][3] = Al[w1 + 4];
        }
        uint32_t bf[8][2];
#pragma unroll
        for (int nt = 0; nt < 8; nt++) {
            int n = (wn << 6) + (nt << 3) + qr;
            int w = n * SW + base + qc;
            bf[nt][0] = Bh[w]; bf[nt][1] = Bh[w + 4];
        }
#pragma unroll
        for (int nt = 0; nt < 8; nt++) {
            mma_f16(acc[0][nt], ah[0], bf[nt][0], bf[nt][1]);
            mma_f16(acc[1][nt], ah[1], bf[nt][0], bf[nt][1]);
        }
#pragma unroll
        for (int nt = 0; nt < 8; nt++) {
            mma_f16(acc[0][nt], al[0], bf[nt][0], bf[nt][1]);
            mma_f16(acc[1][nt], al[1], bf[nt][0], bf[nt][1]);
        }
#pragma unroll
        for (int nt = 0; nt < 8; nt++) {
            int n = (wn << 6) + (nt << 3) + qr;
            int w = n * SW + base + qc;
            bf[nt][0] = Bl[w]; bf[nt][1] = Bl[w + 4];
        }
#pragma unroll
        for (int nt = 0; nt < 8; nt++) {
            mma_f16(acc[0][nt], ah[0], bf[nt][0], bf[nt][1]);
            mma_f16(acc[1][nt], ah[1], bf[nt][0], bf[nt][1]);
        }
    }
}

// ---------------------------------------------------------------------------
// Implicit-GEMM conv via mma.sync fp16x3, 2 CTAs/SM for cross-CTA overlap,
// coalesced direct-build im2col (no register prefetch).
// D[co=128, hw=128] = W[co, K] * P[hw, K], K = CIN*TAPS.
// grid (8 hw-tiles, LOUT, B_), block 256 (8 warps, each 32co x 64hw).
// ---------------------------------------------------------------------------
template<int TAPS, int LOUT>
__global__ __launch_bounds__(256, 2) void conv_mma_kernel(
    const float* __restrict__ in, const float* __restrict__ wgt,
    const float* __restrict__ bias, float* __restrict__ dst, float scale)
{
    constexpr int KSEG = CIN * TAPS;          // 576 or 1728
    constexpr int NCHUNK = KSEG / KC;         // 18 or 54
    __shared__ uint32_t Ah[128*SW], Al[128*SW];        // A: [co][kp]
    __shared__ uint32_t Bh[16*SWB], Bl[16*SWB];        // B: [kp][px]

    const int tid = threadIdx.x;
    const int wid = tid >> 5;
    const int lid = tid & 31;
    const int wm  = wid & 3;
    const int wn  = wid >> 2;
    const int l   = blockIdx.y;
    const int b   = blockIdx.z;
    const int hw0 = blockIdx.x << 7;

    const float* inb = in + (size_t)b*CIN*L_*HW + (size_t)l*HW;

    // A-build mapping: lanes along k (coalesced in wgt)
    const int kp_a = tid & 15;
    const int rw_a = tid >> 4;
    // B-build mapping: lanes along pixels (coalesced in input)
    const int px   = tid & 127;
    const int kq   = tid >> 7;                // 0/1
    const int bh_  = (hw0 + px) >> 5;
    const int bw_  = px & 31;

    float acc[2][8][4];
#pragma unroll
    for (int i = 0; i < 2; i++)
#pragma unroll
        for (int j = 0; j < 8; j++)
#pragma unroll
            for (int r = 0; r < 4; r++) acc[i][j][r] = 0.f;

#pragma unroll 1
    for (int c = 0; c < NCHUNK; c++) {
        const int tb = c * KC;
        // A tile: 128 co x 32 k, direct LDG -> split -> STS (coalesced)
#pragma unroll
        for (int q = 0; q < 8; q++) {
            int row = rw_a + (q << 4);
            float2 v = *(const float2*)(wgt + (size_t)row * KSEG + tb + (kp_a << 1));
            uint32_t hi, lo;
            split2(v.x, v.y, hi, lo);
            Ah[row*SW + kp_a] = hi;
            Al[row*SW + kp_a] = lo;
        }
        // B tile: im2col, lanes sweep pixels (coalesced), fixed (ci,tap)/iter
#pragma unroll
        for (int it = 0; it < 8; it++) {
            int kp = (it << 1) + kq;
            float xv[2];
#pragma unroll
            for (int e = 0; e < 2; e++) {
                int t   = tb + (kp << 1) + e;
                int ci  = t / TAPS;
                int tap = t - ci * TAPS;
                int dl, dh, dw;
                if (TAPS == 27) { dl = tap / 9; int r = tap - dl * 9; dh = r / 3; dw = r - dh * 3; }
                else            { dl = 0; dh = tap / 3; dw = tap - dh * 3; }
                int hh = bh_ + dh - 1, ww = bw_ + dw - 1;
                float x = 0.f;
                if ((unsigned)hh < (unsigned)H_ && (unsigned)ww < (unsigned)W_)
                    x = inb[((size_t)ci * L_ + dl) * HW + hh * W_ + ww];
                xv[e] = x;
            }
            uint32_t hi, lo;
            split2(xv[0], xv[1], hi, lo);
            Bh[kp*SWB + px] = hi;
            Bl[kp*SWB + px] = lo;
        }
        __syncthreads();
        mma_chunk_bk(acc, Ah, Al, Bh, Bl, wm, wn, lid);
        __syncthreads();
    }

    // Epilogue
#pragma unroll
    for (int mt = 0; mt < 2; mt++) {
        int co = (wm << 5) + (mt << 4) + (lid >> 2);
        float bi0 = bias[co];
        float bi1 = bias[co + 8];
        float* d0 = dst + (((size_t)b * COUT + co)     * LOUT + l) * HW + hw0;
        float* d1 = dst + (((size_t)b * COUT + co + 8) * LOUT + l) * HW + hw0;
#pragma unroll
        for (int nt = 0; nt < 8; nt++) {
            int colp = (wn << 6) + (nt << 3) + ((lid & 3) << 1);
            *(float2*)(d0 + colp) = make_float2((acc[mt][nt][0] + bi0) * scale,
                                                (acc[mt][nt][1] + bi0) * scale);
            *(float2*)(d1 + colp) = make_float2((acc[mt][nt][2] + bi1) * scale,
                                                (acc[mt][nt][3] + bi1) * scale);
        }
    }
}

// ---------------------------------------------------------------------------
// Logit partial per (ck, b, n, d): D[c=128, m=128] = sum over 512 pixels.
// grid KSPL*144, block 256, 2 CTAs/SM, direct build.
// ---------------------------------------------------------------------------
__global__ __launch_bounds__(256, 2) void logit_mma_kernel(
    const float* __restrict__ q, const float* __restrict__ k, float* __restrict__ lp)
{
    constexpr int NCHUNK = HW / (KC * KSPL);  // 16
    __shared__ uint32_t Ah[128*SW], Al[128*SW], Bh[128*SW], Bl[128*SW];

    const int tid = threadIdx.x;
    const int wid = tid >> 5;
    const int lid = tid & 31;
    const int wm  = wid & 3;
    const int wn  = wid >> 2;
    const int ck  = blockIdx.x / (B_*NH*DQ);
    const int bnd = blockIdx.x % (B_*NH*DQ);
    const int d   = bnd % DQ;
    const int bn  = bnd / DQ;
    const int n_  = bn & 1;
    const int b   = bn >> 1;
    const int ldep = n_ * DQ + d;

    const float* qb = q + ((size_t)b * COUT * L_ + ldep) * HW;
    const float* kb = k + ((size_t)b * COUT * L_ + ldep) * HW;

    float acc[2][8][4];
#pragma unroll
    for (int i = 0; i < 2; i++)
#pragma unroll
        for (int j = 0; j < 8; j++)
#pragma unroll
            for (int r = 0; r < 4; r++) acc[i][j][r] = 0.f;

    const int kp_b = tid & 15;
    const int rw_b = tid >> 4;
    const int base0 = ck * (HW/KSPL);

#pragma unroll 1
    for (int c = 0; c < NCHUNK; c++) {
        const int tb = base0 + c * KC;
#pragma unroll
        for (int qq = 0; qq < 8; qq++) {
            int row = rw_b + (qq << 4);
            float2 va = *(const float2*)(qb + (size_t)row * (L_*HW) + tb + (kp_b << 1));
            uint32_t hi, lo;
            split2(va.x, va.y, hi, lo);
            Ah[row*SW + kp_b] = hi;
            Al[row*SW + kp_b] = lo;
            float2 vb = *(const float2*)(kb + (size_t)row * (L_*HW) + tb + (kp_b << 1));
            split2(vb.x, vb.y, hi, lo);
            Bh[row*SW + kp_b] = hi;
            Bl[row*SW + kp_b] = lo;
        }
        __syncthreads();
        mma_chunk(acc, Ah, Al, Bh, Bl, wm, wn, lid);
        __syncthreads();
    }

    float* o = lp + (size_t)blockIdx.x * COUT * COUT;
#pragma unroll
    for (int mt = 0; mt < 2; mt++) {
        int cc = (wm << 5) + (mt << 4) + (lid >> 2);
#pragma unroll
        for (int nt = 0; nt < 8; nt++) {
            int m = (wn << 6) + (nt << 3) + ((lid & 3) << 1);
            *(float2*)(o + (size_t)cc * COUT + m) =
                make_float2(acc[mt][nt][0], acc[mt][nt][1]);
            *(float2*)(o + (size_t)(cc + 8) * COUT + m) =
                make_float2(acc[mt][nt][2], acc[mt][nt][3]);
        }
    }
}

// ---------------------------------------------------------------------------
// Sum KSPL*DQ partials + row softmax over m. One block per (bn, c).
// ---------------------------------------------------------------------------
__global__ __launch_bounds__(128) void softmax_kernel(
    const float* __restrict__ lp, float* __restrict__ attn)
{
    const int row = blockIdx.x;
    const int bn  = row >> 7;
    const int c   = row & 127;
    const int m   = threadIdx.x;

    float s = 0.f;
#pragma unroll
    for (int ch = 0; ch < KSPL; ch++)
#pragma unroll
        for (int dd = 0; dd < DQ; dd++)
            s += lp[(((size_t)(ch*(B_*NH*DQ) + bn*DQ + dd))*COUT + c)*COUT + m];

    __shared__ float red[128];
    red[m] = s;
    __syncthreads();
    for (int off = 64; off > 0; off >>= 1) {
        if (m < off) red[m] = fmaxf(red[m], red[m + off]);
        __syncthreads();
    }
    float mx = red[0];
    __syncthreads();
    float e = expf(s - mx);
    red[m] = e;
    __syncthreads();
    for (int off = 64; off > 0; off >>= 1) {
        if (m < off) red[m] = red[m] + red[m + off];
        __syncthreads();
    }
    attn[row*COUT + m] = e / red[0];
}

// ---------------------------------------------------------------------------
// out[b,c,n*8+d,hw] = sum_m attn[bn,c,m] * v[b,m,n*8+d,hw]  (f32x2 scalar)
// ---------------------------------------------------------------------------
__global__ __launch_bounds__(256) void out_kernel(
    const float* __restrict__ attn, const float* __restrict__ v, float* __restrict__ out)
{
    const int tile = blockIdx.x;
    const int bn   = blockIdx.y;
    const int b    = bn >> 1;
    const int n    = bn & 1;
    const int d    = (tile << 6) >> 10;
    const int hw0  = (tile << 6) & 1023;
    const int tid  = threadIdx.x;
    const int px   = tid & 63;
    const int cg   = tid >> 6;
    const int c0   = cg << 5;
    const int hw   = hw0 + px;

    __shared__ float As2[64*132];
    const float* ab = attn + bn*COUT*COUT;
    const float* vb = v + ((size_t)b*COUT*LV + n*DV + d)*HW + hw;

    ull acc2[16];
#pragma unroll
    for (int j = 0; j < 16; j++) acc2[j] = 0ull;

    for (int mc = 0; mc < 2; mc++) {
        __syncthreads();
        for (int i = tid; i < 64*128; i += 256) {
            int ml = i & 63;
            int c  = i >> 6;
            As2[ml*132 + c] = ab[c*COUT + (mc << 6) + ml];
        }
        __syncthreads();
#pragma unroll 4
        for (int ml = 0; ml < 64; ml++) {
            float vv = vb[((size_t)((mc << 6) + ml))*(LV*HW)];
            ull vp = pack2(vv, vv);
            const ull* ap = (const ull*)&As2[ml*132 + c0];
#pragma unroll
            for (int jj = 0; jj < 16; jj++)
                ffma2(acc2[jj], ap[jj], vp);
        }
    }
    float* ob = out + (((size_t)b*COUT + c0)*(NH*DV) + n*DV + d)*HW + hw;
#pragma unroll
    for (int jj = 0; jj < 16; jj++) {
        float2 a = unpack2(acc2[jj]);
        ob[(size_t)(2*jj)    *(NH*DV*HW)] = a.x;
        ob[(size_t)(2*jj + 1)*(NH*DV*HW)] = a.y;
    }
}

// ---------------------------------------------------------------------------
extern "C" void kernel_launch(void* const* d_in, const int* in_sizes, int n_in,
                              void* d_out, int out_size)
{
    const float* input  = (const float*)d_in[0];
    const float* memory = (const float*)d_in[1];
    const float* wq = (const float*)d_in[2];
    const float* bq = (const float*)d_in[3];
    const float* wk = (const float*)d_in[4];
    const float* bk = (const float*)d_in[5];
    const float* wv = (const float*)d_in[6];
    const float* bv = (const float*)d_in[7];
    float* out = (float*)d_out;

    float *pq, *pk, *pv, *plp, *pattn;
    cudaGetSymbolAddress((void**)&pq,    g_q);
    cudaGetSymbolAddress((void**)&pk,    g_k);
    cudaGetSymbolAddress((void**)&pv,    g_v);
    cudaGetSymbolAddress((void**)&plp,   g_lp);
    cudaGetSymbolAddress((void**)&pattn, g_attn);

    conv_mma_kernel<9, L_> <<<dim3(8, L_, B_), 256>>>(input,  wq, bq, pq, 0.5f);
    conv_mma_kernel<9, L_> <<<dim3(8, L_, B_), 256>>>(memory, wk, bk, pk, 1.0f);
    conv_mma_kernel<27, LV><<<dim3(8, LV, B_), 256>>>(memory, wv, bv, pv, 1.0f);
    logit_mma_kernel       <<<KSPL*B_*NH*DQ, 256>>>(pq, pk, plp);
    softmax_kernel         <<<B_*NH*COUT, 128>>>(plp, pattn);
    out_kernel             <<<dim3(128, B_*NH), 256>>>(pattn, pv, out);
}